// round 13
// baseline (speedup 1.0000x reference)
#include <cuda_runtime.h>
#include <cuda_fp16.h>

#define N_  4
#define C_  128
#define HW_ 4096
#define W_  64

union Pack4 {
    uint4   u;
    __half2 h[4];
};

// ---------------------------------------------------------------------------
// Single fused kernel, intra-block pipelined. 128 blocks x 1024 threads,
// one block per (n, channel-quad). Channels processed as two PAIRS with
// separate smem buffers so pair1's DRAM latency hides behind pair0's gather:
//   [LDG taps, pair0, pair1]  STS s0 | bar | gather0+STG | STS s1 | bar |
//   gather1+STG
// Smem: sX[j] = half2(x[chA][j], x[chB][j]) -> one LDS.32 per corner serves
// 2 channels. Thread t: 4 consecutive positions 4t..4t+3 (all gmem 128-bit).
// out = w0*x[c] + w1*x[c+1] + w2*x[c+64] + w3*x[c+65],
// w = outer([1-fx, fx], [fx, fy]) * valid  (valid over ALL 4 grids)
// ---------------------------------------------------------------------------
__global__ __launch_bounds__(1024, 1)
void fused_kernel(const float* __restrict__ x,
                  const float* __restrict__ grid,
                  float* __restrict__ out) {
    __shared__ __half2 s0[HW_];   // 16 KB: (ch0, ch1)
    __shared__ __half2 s1[HW_];   // 16 KB: (ch2, ch3)

    const int tid = threadIdx.x;          // 0..1023
    const int n   = blockIdx.x >> 5;      // 0..3
    const int ch0 = (blockIdx.x & 31) * 4;

    const float4* r0 = (const float4*)(x + (size_t)(n * C_ + ch0 + 0) * HW_);
    const float4* r1 = (const float4*)(x + (size_t)(n * C_ + ch0 + 1) * HW_);
    const float4* r2 = (const float4*)(x + (size_t)(n * C_ + ch0 + 2) * HW_);
    const float4* r3 = (const float4*)(x + (size_t)(n * C_ + ch0 + 3) * HW_);

    // ---- tap loads first (needed right after barrier1)
    const float4* g4 = (const float4*)grid;   // grid row r: r*HW_/2 float4s
    float4 G[4][2];
#pragma unroll
    for (int r = 0; r < 4; ++r) {
        G[r][0] = __ldg(g4 + r * (HW_ / 2) + 2 * tid);
        G[r][1] = __ldg(g4 + r * (HW_ / 2) + 2 * tid + 1);
    }

    // ---- x loads: pair0 then pair1 (pair1 latency hides behind gather0)
    float4 v0 = __ldg(r0 + tid);
    float4 v1 = __ldg(r1 + tid);
    float4 v2 = __ldg(r2 + tid);
    float4 v3 = __ldg(r3 + tid);

    // ---- stage pair0 (one STS.128, conflict-free)
    {
        Pack4 pk;
        pk.h[0] = __floats2half2_rn(v0.x, v1.x);
        pk.h[1] = __floats2half2_rn(v0.y, v1.y);
        pk.h[2] = __floats2half2_rn(v0.z, v1.z);
        pk.h[3] = __floats2half2_rn(v0.w, v1.w);
        *(uint4*)&s0[4 * tid] = pk.u;
    }

    // ---- tap math (register-only; overlaps outstanding loads)
    int   c0[4];
    float fx[4], fy[4];
#pragma unroll
    for (int p = 0; p < 4; ++p) {
        float2 gg[4];
#pragma unroll
        for (int r = 0; r < 4; ++r) {
            float4 h = G[r][p >> 1];
            gg[r] = (p & 1) ? make_float2(h.z, h.w) : make_float2(h.x, h.y);
        }
        bool valid = true;
#pragma unroll
        for (int r = 0; r < 4; ++r)
            valid = valid && (gg[r].x >= -0.001f) && (gg[r].x <= 63.001f)
                          && (gg[r].y >= -0.001f) && (gg[r].y <= 63.001f);
        float2 go = gg[n];
        float xx = fminf(fmaxf(go.x, 0.001f), 62.999f);
        float yy = fminf(fmaxf(go.y, 0.001f), 62.999f);
        float flx = floorf(xx);
        float fly = floorf(yy);
        c0[p] = (int)flx * W_ + (int)fly;
        fx[p] = valid ? (xx - flx) : 0.f;
        fy[p] = valid ? (yy - fly) : 0.f;
    }

    float4* ob = (float4*)(out + (size_t)(n * C_ + ch0) * HW_);
    const int q = HW_ / 4;

    __syncthreads();   // barrier1: s0 ready

    // ---- gather pair0 (ch0, ch1) from s0; pair1 LDGs still in flight
    {
        float4 oa, obv;
        float* pa = (float*)&oa;
        float* pb = (float*)&obv;
#pragma unroll
        for (int p = 0; p < 4; ++p) {
            int c = c0[p];
            float2 t0 = __half22float2(s0[c]);
            float2 t1 = __half22float2(s0[c + 1]);
            float2 t2 = __half22float2(s0[c + 64]);
            float2 t3 = __half22float2(s0[c + 65]);
            float w0 = (1.f - fx[p]) * fx[p];
            float w1 = (1.f - fx[p]) * fy[p];
            float w2 = fx[p] * fx[p];
            float w3 = fx[p] * fy[p];
            pa[p] = w0 * t0.x + w1 * t1.x + w2 * t2.x + w3 * t3.x;
            pb[p] = w0 * t0.y + w1 * t1.y + w2 * t2.y + w3 * t3.y;
        }
        ob[0 * q + tid] = oa;
        ob[1 * q + tid] = obv;
    }

    // ---- stage pair1 into s1 (different buffer: no WAR with s0 reads)
    {
        Pack4 pk;
        pk.h[0] = __floats2half2_rn(v2.x, v3.x);
        pk.h[1] = __floats2half2_rn(v2.y, v3.y);
        pk.h[2] = __floats2half2_rn(v2.z, v3.z);
        pk.h[3] = __floats2half2_rn(v2.w, v3.w);
        *(uint4*)&s1[4 * tid] = pk.u;
    }
    __syncthreads();   // barrier2: s1 ready

    // ---- gather pair1 (ch2, ch3) from s1
    {
        float4 oa, obv;
        float* pa = (float*)&oa;
        float* pb = (float*)&obv;
#pragma unroll
        for (int p = 0; p < 4; ++p) {
            int c = c0[p];
            float2 t0 = __half22float2(s1[c]);
            float2 t1 = __half22float2(s1[c + 1]);
            float2 t2 = __half22float2(s1[c + 64]);
            float2 t3 = __half22float2(s1[c + 65]);
            float w0 = (1.f - fx[p]) * fx[p];
            float w1 = (1.f - fx[p]) * fy[p];
            float w2 = fx[p] * fx[p];
            float w3 = fx[p] * fy[p];
            pa[p] = w0 * t0.x + w1 * t1.x + w2 * t2.x + w3 * t3.x;
            pb[p] = w0 * t0.y + w1 * t1.y + w2 * t2.y + w3 * t3.y;
        }
        ob[2 * q + tid] = oa;
        ob[3 * q + tid] = obv;
    }
}

extern "C" void kernel_launch(void* const* d_in, const int* in_sizes, int n_in,
                              void* d_out, int out_size) {
    const float* x    = (const float*)d_in[0];   // (4, 128, 4096) f32
    const float* grid = (const float*)d_in[1];   // (4, 64, 64, 2) f32
    float* out = (float*)d_out;                  // (4, 128, 4096) f32

    fused_kernel<<<N_ * (C_ / 4), 1024>>>(x, grid, out);
}

// round 14
// speedup vs baseline: 1.7380x; 1.7380x over previous
#include <cuda_runtime.h>
#include <cuda_fp16.h>

#define N_  4
#define C_  128
#define HW_ 4096
#define W_  64

union Half4 {
    uint2   u;
    __half2 h[2];
};

// ---------------------------------------------------------------------------
// Single fused kernel, cluster-shared validity.
// 32 clusters x 4 CTAs (rank = n), 1024 threads/CTA; CTA = (n, channel-quad).
// Each CTA reads ONLY its own grid row; the .all(0) validity across the 4
// grids is assembled by exchanging 512-byte bitmasks over DSMEM and ANDing.
// One barrier.cluster (release/acquire) orders both the mask exchange and the
// local x-tile STS -- no separate __syncthreads needed.
// Smem tile: s[j] = half4(x[ch0..ch0+3][j]) -> one LDS.64 per corner serves
// 4 channels. Thread t: positions 4t..4t+3; all gmem ops 128-bit.
// out = w0*x[c] + w1*x[c+1] + w2*x[c+64] + w3*x[c+65],
// w = outer([1-fx, fx], [fx, fy]) * valid
// ---------------------------------------------------------------------------
__global__ __launch_bounds__(1024, 1) __cluster_dims__(4, 1, 1)
void fused_kernel(const float* __restrict__ x,
                  const float* __restrict__ grid,
                  float* __restrict__ out) {
    __shared__ uint2    s[HW_];      // 32 KB: half4 per position
    __shared__ unsigned vm[4][128];  // 2 KB: per-rank validity bitmasks

    const int tid = threadIdx.x;        // 0..1023
    const int bid = blockIdx.x;         // 0..127
    const int n   = bid & 3;            // cluster rank == grid index
    const int ch0 = (bid >> 2) * 4;     // channel-quad base

    const float4* r0 = (const float4*)(x + (size_t)(n * C_ + ch0 + 0) * HW_);
    const float4* r1 = (const float4*)(x + (size_t)(n * C_ + ch0 + 1) * HW_);
    const float4* r2 = (const float4*)(x + (size_t)(n * C_ + ch0 + 2) * HW_);
    const float4* r3 = (const float4*)(x + (size_t)(n * C_ + ch0 + 3) * HW_);

    // ---- x staging loads (4x LDG.128, issue first)
    float4 v0 = __ldg(r0 + tid);
    float4 v1 = __ldg(r1 + tid);
    float4 v2 = __ldg(r2 + tid);
    float4 v3 = __ldg(r3 + tid);

    // ---- own grid row only (2x LDG.128): positions 4t..4t+3
    const float4* g4 = (const float4*)grid;
    float4 G0 = __ldg(g4 + n * (HW_ / 2) + 2 * tid);       // pos 4t, 4t+1
    float4 G1 = __ldg(g4 + n * (HW_ / 2) + 2 * tid + 1);   // pos 4t+2, 4t+3

    // ---- own-row in-range nibble (bit b = position 4t+b in range)
    unsigned nib =
        ((G0.x >= -0.001f && G0.x <= 63.001f && G0.y >= -0.001f && G0.y <= 63.001f) ? 1u : 0u) |
        ((G0.z >= -0.001f && G0.z <= 63.001f && G0.w >= -0.001f && G0.w <= 63.001f) ? 2u : 0u) |
        ((G1.x >= -0.001f && G1.x <= 63.001f && G1.y >= -0.001f && G1.y <= 63.001f) ? 4u : 0u) |
        ((G1.z >= -0.001f && G1.z <= 63.001f && G1.w >= -0.001f && G1.w <= 63.001f) ? 8u : 0u);

    // ---- assemble 32-position words within 8-lane groups (no atomics)
    unsigned wv = nib << (4 * (tid & 7));
    wv |= __shfl_xor_sync(0xFFFFFFFFu, wv, 4);
    wv |= __shfl_xor_sync(0xFFFFFFFFu, wv, 2);
    wv |= __shfl_xor_sync(0xFFFFFFFFu, wv, 1);
    if ((tid & 7) == 0) {
        int w = tid >> 3;                 // word index 0..127
        vm[n][w] = wv;                    // local copy
        unsigned la = (unsigned)__cvta_generic_to_shared(&vm[n][w]);
#pragma unroll
        for (int r = 0; r < 4; ++r) {
            if (r != n) {
                unsigned ra;
                asm volatile("mapa.shared::cluster.u32 %0, %1, %2;"
                             : "=r"(ra) : "r"(la), "r"(r));
                asm volatile("st.shared::cluster.u32 [%0], %1;"
                             :: "r"(ra), "r"(wv) : "memory");
            }
        }
    }

    // ---- stage x as half4 quads (2x STS.128, conflict-free)
    {
        Half4 q0, q1, q2, q3;
        q0.h[0] = __floats2half2_rn(v0.x, v1.x);  q0.h[1] = __floats2half2_rn(v2.x, v3.x);
        q1.h[0] = __floats2half2_rn(v0.y, v1.y);  q1.h[1] = __floats2half2_rn(v2.y, v3.y);
        q2.h[0] = __floats2half2_rn(v0.z, v1.z);  q2.h[1] = __floats2half2_rn(v2.z, v3.z);
        q3.h[0] = __floats2half2_rn(v0.w, v1.w);  q3.h[1] = __floats2half2_rn(v2.w, v3.w);
        uint4* sd = (uint4*)&s[4 * tid];
        sd[0] = make_uint4(q0.u.x, q0.u.y, q1.u.x, q1.u.y);
        sd[1] = make_uint4(q2.u.x, q2.u.y, q3.u.x, q3.u.y);
    }

    // ---- tap math from own row (validity applied after cluster sync)
    int   c0[4];
    float fx[4], fy[4];
#pragma unroll
    for (int p = 0; p < 4; ++p) {
        float2 go = (p == 0) ? make_float2(G0.x, G0.y)
                  : (p == 1) ? make_float2(G0.z, G0.w)
                  : (p == 2) ? make_float2(G1.x, G1.y)
                  :            make_float2(G1.z, G1.w);
        float xx = fminf(fmaxf(go.x, 0.001f), 62.999f);
        float yy = fminf(fmaxf(go.y, 0.001f), 62.999f);
        float flx = floorf(xx);
        float fly = floorf(yy);
        c0[p] = (int)flx * W_ + (int)fly;
        fx[p] = xx - flx;
        fy[p] = yy - fly;
    }

    // ---- cluster barrier: release our (mask + tile) stores, acquire peers'
    asm volatile("barrier.cluster.arrive.aligned;" ::: "memory");
    asm volatile("barrier.cluster.wait.aligned;"   ::: "memory");

    // ---- fold validity (AND of all 4 ranks)
    {
        int w  = tid >> 3;
        int sh = 4 * (tid & 7);
        unsigned va = vm[0][w] & vm[1][w] & vm[2][w] & vm[3][w];
        unsigned nb = (va >> sh) & 0xFu;
#pragma unroll
        for (int p = 0; p < 4; ++p) {
            if (!((nb >> p) & 1u)) { fx[p] = 0.f; fy[p] = 0.f; }
        }
    }

    // ---- gather + math: per position 4 corners (LDS.64), fp32 accumulate
    float4 oc0, oc1, oc2, oc3;
    float* po0 = (float*)&oc0;
    float* po1 = (float*)&oc1;
    float* po2 = (float*)&oc2;
    float* po3 = (float*)&oc3;
#pragma unroll
    for (int p = 0; p < 4; ++p) {
        int c = c0[p];
        Half4 t0, t1, t2, t3;
        t0.u = s[c];
        t1.u = s[c + 1];
        t2.u = s[c + 64];
        t3.u = s[c + 65];

        float w0 = (1.f - fx[p]) * fx[p];
        float w1 = (1.f - fx[p]) * fy[p];
        float w2 = fx[p] * fx[p];
        float w3 = fx[p] * fy[p];

        float2 a01 = __half22float2(t0.h[0]), a23 = __half22float2(t0.h[1]);
        float2 b01 = __half22float2(t1.h[0]), b23 = __half22float2(t1.h[1]);
        float2 c01 = __half22float2(t2.h[0]), c23 = __half22float2(t2.h[1]);
        float2 d01 = __half22float2(t3.h[0]), d23 = __half22float2(t3.h[1]);

        po0[p] = w0 * a01.x + w1 * b01.x + w2 * c01.x + w3 * d01.x;
        po1[p] = w0 * a01.y + w1 * b01.y + w2 * c01.y + w3 * d01.y;
        po2[p] = w0 * a23.x + w1 * b23.x + w2 * c23.x + w3 * d23.x;
        po3[p] = w0 * a23.y + w1 * b23.y + w2 * c23.y + w3 * d23.y;
    }

    float4* ob = (float4*)(out + (size_t)(n * C_ + ch0) * HW_);
    const int q = HW_ / 4;
    ob[0 * q + tid] = oc0;
    ob[1 * q + tid] = oc1;
    ob[2 * q + tid] = oc2;
    ob[3 * q + tid] = oc3;
}

extern "C" void kernel_launch(void* const* d_in, const int* in_sizes, int n_in,
                              void* d_out, int out_size) {
    const float* x    = (const float*)d_in[0];   // (4, 128, 4096) f32
    const float* grid = (const float*)d_in[1];   // (4, 64, 64, 2) f32
    float* out = (float*)d_out;                  // (4, 128, 4096) f32

    fused_kernel<<<N_ * (C_ / 4), 1024>>>(x, grid, out);
}